// round 1
// baseline (speedup 1.0000x reference)
#include <cuda_runtime.h>
#include <cuda_bf16.h>

#define NNODES 50000
#define FDIM   256
#define KMIX   5

// ---------------- scratch (static device allocations) ----------------
__device__ float g_S0[NNODES * FDIM];     // = X0 + scatter-add of X0[src]   (51.2 MB)
__device__ float g_SM[NNODES * FDIM];     // = mask + scatter-add of mask[src]
__device__ float g_indeg[NNODES];
__device__ float g_gamma[NNODES * KMIX];
__device__ int   g_flags[2];              // [0]: mask is 1-byte?  [1]: edges are int64?

// ---------------- dtype detection (mask bool-vs-int32, edges i64-vs-i32) ----
__global__ void detect_kernel(const void* mask, const void* edges) {
    int t = threadIdx.x;
    int any_m = 0, any_e = 0;
    const unsigned char* mb = (const unsigned char*)mask;
    const int* ei = (const int*)edges;
    for (int i = t; i < 4096; i += 256) {
        if (mb[4 * i + 1] != 0) any_m = 1;   // random bool bytes -> nonzero; int32 {0,1} byte1 always 0
        if (ei[2 * i + 1] != 0) any_e = 1;   // int64 high words are 0; int32 values mostly nonzero
    }
    any_m = __syncthreads_or(any_m);
    any_e = __syncthreads_or(any_e);
    if (t == 0) {
        g_flags[0] = any_m ? 1 : 0;   // 1 => mask stored as 1-byte bool
        g_flags[1] = any_e ? 0 : 1;   // 1 => edges stored as int64
    }
}

// ---------------- zero scratch ----------------
__global__ void zero_kernel() {
    int i = blockIdx.x * blockDim.x + threadIdx.x;   // 0 .. 3.2M-1 (float4 count)
    const int total4 = NNODES * FDIM / 4;
    float4 z = make_float4(0.f, 0.f, 0.f, 0.f);
    if (i < total4) {
        ((float4*)g_S0)[i] = z;
        ((float4*)g_SM)[i] = z;
    }
    if (i < NNODES) g_indeg[i] = 0.f;
}

// ---------------- gamma (softmax mixture weights) ----------------
__global__ void gamma_kernel(const float* __restrict__ x, const void* __restrict__ mask,
                             const float* __restrict__ logp, const float* __restrict__ means,
                             const float* __restrict__ logvars) {
    int n = blockIdx.x;
    int f = threadIdx.x;   // 256 threads
    int mbyte = g_flags[0];
    float xv = x[n * FDIM + f];
    int m = mbyte ? (int)((const unsigned char*)mask)[n * FDIM + f]
                  : ((const int*)mask)[n * FDIM + f];
    float q[KMIX];
#pragma unroll
    for (int k = 0; k < KMIX; k++) {
        float d = xv - means[k * FDIM + f];
        float iv = expf(-logvars[k * FDIM + f]);
        q[k] = m ? 0.0f : d * d * iv;
    }
#pragma unroll
    for (int k = 0; k < KMIX; k++)
        for (int off = 16; off; off >>= 1)
            q[k] += __shfl_down_sync(0xffffffffu, q[k], off);

    __shared__ float red[8][KMIX];
    int w = f >> 5, lane = f & 31;
    if (lane == 0)
#pragma unroll
        for (int k = 0; k < KMIX; k++) red[w][k] = q[k];
    __syncthreads();
    if (f == 0) {
        float l[KMIX], mx = -1e30f;
#pragma unroll
        for (int k = 0; k < KMIX; k++) {
            float s = 0.f;
            for (int ww = 0; ww < 8; ww++) s += red[ww][k];
            l[k] = logp[k] - 0.5f * s;
            mx = fmaxf(mx, l[k]);
        }
        float e[KMIX], se = 0.f;
#pragma unroll
        for (int k = 0; k < KMIX; k++) { e[k] = expf(l[k] - mx); se += e[k]; }
        float inv = 1.0f / se;
#pragma unroll
        for (int k = 0; k < KMIX; k++) g_gamma[n * KMIX + k] = e[k] * inv;
    }
}

// ---------------- base: S0 += x*(1-mask), SM += mask ----------------
__global__ void base_kernel(const float* __restrict__ x, const void* __restrict__ mask) {
    int i = blockIdx.x * blockDim.x + threadIdx.x;   // < 12.8M
    int m = g_flags[0] ? (int)((const unsigned char*)mask)[i]
                       : ((const int*)mask)[i];
    float xv = x[i];
    g_S0[i] += m ? 0.0f : xv;
    g_SM[i] += m ? 1.0f : 0.0f;
}

// ---------------- edge scatter-add (one warp per edge) ----------------
__device__ __forceinline__ void red4(float* p, float a, float b, float c, float d) {
    asm volatile("red.global.add.v4.f32 [%0], {%1,%2,%3,%4};"
                 :: "l"(p), "f"(a), "f"(b), "f"(c), "f"(d) : "memory");
}

__global__ void edge_kernel(const float* __restrict__ x, const void* __restrict__ mask,
                            const void* __restrict__ edges, int E) {
    int gw = (blockIdx.x * blockDim.x + threadIdx.x) >> 5;
    int lane = threadIdx.x & 31;
    if (gw >= E) return;
    int src, dst;
    if (g_flags[1]) {
        const long long* e = (const long long*)edges;
        src = (int)e[gw]; dst = (int)e[E + gw];
    } else {
        const int* e = (const int*)edges;
        src = e[gw]; dst = e[E + gw];
    }
    const float4* xs = (const float4*)(x + (size_t)src * FDIM);
    float4 a0 = xs[lane];
    float4 a1 = xs[lane + 32];

    int4 mi0, mi1;
    if (g_flags[0]) {
        const uchar4* mm = (const uchar4*)((const unsigned char*)mask + (size_t)src * FDIM);
        uchar4 u0 = mm[lane], u1 = mm[lane + 32];
        mi0 = make_int4(u0.x, u0.y, u0.z, u0.w);
        mi1 = make_int4(u1.x, u1.y, u1.z, u1.w);
    } else {
        const int4* mm = (const int4*)((const int*)mask + (size_t)src * FDIM);
        mi0 = mm[lane]; mi1 = mm[lane + 32];
    }

    float* S0p = g_S0 + (size_t)dst * FDIM;
    float* SMp = g_SM + (size_t)dst * FDIM;

    red4(S0p + 4 * lane,
         mi0.x ? 0.f : a0.x, mi0.y ? 0.f : a0.y, mi0.z ? 0.f : a0.z, mi0.w ? 0.f : a0.w);
    red4(S0p + 128 + 4 * lane,
         mi1.x ? 0.f : a1.x, mi1.y ? 0.f : a1.y, mi1.z ? 0.f : a1.z, mi1.w ? 0.f : a1.w);
    red4(SMp + 4 * lane,
         mi0.x ? 1.f : 0.f, mi0.y ? 1.f : 0.f, mi0.z ? 1.f : 0.f, mi0.w ? 1.f : 0.f);
    red4(SMp + 128 + 4 * lane,
         mi1.x ? 1.f : 0.f, mi1.y ? 1.f : 0.f, mi1.z ? 1.f : 0.f, mi1.w ? 1.f : 0.f);
    if (lane == 0) atomicAdd(&g_indeg[dst], 1.0f);
}

// ---------------- fused GEMM + ex_relu + mixture epilogue ----------------
__device__ __forceinline__ float ex_relu(float mu, float s) {
    if (s <= 0.0f) return fmaxf(mu, 0.0f);
    float ss = sqrtf(s);
    float w  = mu / ss;
    return ss * (0.3989422804014327f * expf(-0.5f * w * w)
                 + 0.5f * w * (1.0f + erff(w * 0.7071067811865476f)));
}

#define GN 64
#define GO 32
#define GF 32

__global__ __launch_bounds__(256) void gemm_epi_kernel(
    const float* __restrict__ W, const float* __restrict__ bias,
    const float* __restrict__ means, const float* __restrict__ logvars,
    float* __restrict__ out)
{
    __shared__ float As0[GN][GF + 1];
    __shared__ float Asm[GN][GF + 1];
    __shared__ float Wsf[GF][GO];
    __shared__ float ms[KMIX][GF];
    __shared__ float vs[KMIX][GF];

    int nb = blockIdx.x * GN;
    int ob = blockIdx.y * GO;
    int t  = threadIdx.x;
    int tx = t & 15;       // 16 out-pairs -> 32 outs
    int ty = t >> 4;       // 16 node-quads -> 64 nodes

    float t0[4][2] = {};
    float tm[KMIX][4][2] = {};
    float tv[KMIX][4][2] = {};

    for (int ff = 0; ff < FDIM; ff += GF) {
        // A tiles: 64x32 floats each -> 512 float4 per array, 2 per thread
#pragma unroll
        for (int j = 0; j < 2; j++) {
            int id = t + j * 256;
            int r = id >> 3;
            int c = (id & 7) << 2;
            int node = nb + r;
            float4 v0, vm;
            if (node < NNODES) {
                v0 = *(const float4*)&g_S0[(size_t)node * FDIM + ff + c];
                vm = *(const float4*)&g_SM[(size_t)node * FDIM + ff + c];
            } else {
                v0 = make_float4(0.f, 0.f, 0.f, 0.f);
                vm = v0;
            }
            As0[r][c] = v0.x; As0[r][c + 1] = v0.y; As0[r][c + 2] = v0.z; As0[r][c + 3] = v0.w;
            Asm[r][c] = vm.x; Asm[r][c + 1] = vm.y; Asm[r][c + 2] = vm.z; Asm[r][c + 3] = vm.w;
        }
        // W tile 32x32
        {
            int r = t >> 3;
            int c = (t & 7) << 2;
            float4 wv = *(const float4*)&W[(size_t)(ff + r) * FDIM + ob + c];
            *(float4*)&Wsf[r][c] = wv;
        }
        // per-k means / vars slices
        if (t < KMIX * GF) {
            int k = t >> 5, j = t & 31;
            ms[k][j] = means[k * FDIM + ff + j];
            vs[k][j] = expf(logvars[k * FDIM + ff + j]);
        }
        __syncthreads();

#pragma unroll
        for (int fj = 0; fj < GF; fj++) {
            float2 wp = *(const float2*)&Wsf[fj][tx << 1];
            float w0 = wp.x, w1 = wp.y;
            float w0s = w0 * w0, w1s = w1 * w1;
            float a0[4], am[4];
#pragma unroll
            for (int i = 0; i < 4; i++) {
                a0[i] = As0[(ty << 2) + i][fj];
                am[i] = Asm[(ty << 2) + i][fj];
            }
#pragma unroll
            for (int i = 0; i < 4; i++) {
                t0[i][0] += a0[i] * w0;
                t0[i][1] += a0[i] * w1;
            }
#pragma unroll
            for (int k = 0; k < KMIX; k++) {
                float mk = ms[k][fj], vk = vs[k][fj];
                float wk0 = w0 * mk,  wk1 = w1 * mk;
                float wv0 = w0s * vk, wv1 = w1s * vk;
#pragma unroll
                for (int i = 0; i < 4; i++) {
                    tm[k][i][0] += am[i] * wk0;
                    tm[k][i][1] += am[i] * wk1;
                    tv[k][i][0] += am[i] * wv0;
                    tv[k][i][1] += am[i] * wv1;
                }
            }
        }
        __syncthreads();
    }

    // epilogue
#pragma unroll
    for (int i = 0; i < 4; i++) {
        int node = nb + (ty << 2) + i;
        if (node >= NNODES) continue;
        float deg1 = 1.0f + g_indeg[node];
        float g[KMIX];
#pragma unroll
        for (int k = 0; k < KMIX; k++) g[k] = g_gamma[node * KMIX + k];
#pragma unroll
        for (int o = 0; o < 2; o++) {
            int oo = ob + (tx << 1) + o;
            float bb = bias[oo] * deg1;
            float acc = 0.f;
#pragma unroll
            for (int k = 0; k < KMIX; k++) {
                float mu = t0[i][o] + tm[k][i][o] + bb;
                float sg = tv[k][i][o];
                acc += g[k] * ex_relu(mu, sg);
            }
            out[(size_t)node * FDIM + oo] = acc;
        }
    }
}

// ---------------- launcher ----------------
extern "C" void kernel_launch(void* const* d_in, const int* in_sizes, int n_in,
                              void* d_out, int out_size) {
    const float* x       = (const float*)d_in[0];
    const void*  edges   = d_in[1];
    const void*  mask    = d_in[2];
    const float* logp    = (const float*)d_in[3];
    const float* means   = (const float*)d_in[4];
    const float* logvars = (const float*)d_in[5];
    const float* W       = (const float*)d_in[6];
    const float* bias    = (const float*)d_in[7];
    float* out = (float*)d_out;

    int E = in_sizes[1] / 2;

    detect_kernel<<<1, 256>>>(mask, edges);

    int zgrid = (NNODES * FDIM / 4 + 255) / 256;
    zero_kernel<<<zgrid, 256>>>();

    gamma_kernel<<<NNODES, 256>>>(x, mask, logp, means, logvars);

    base_kernel<<<(NNODES * FDIM) / 256, 256>>>(x, mask);

    int eblocks = (E * 32 + 255) / 256;
    edge_kernel<<<eblocks, 256>>>(x, mask, edges, E);

    dim3 ggrid((NNODES + GN - 1) / GN, FDIM / GO);
    gemm_epi_kernel<<<ggrid, 256>>>(W, bias, means, logvars, out);
}

// round 2
// speedup vs baseline: 1.1539x; 1.1539x over previous
#include <cuda_runtime.h>
#include <cuda_bf16.h>

#define NNODES 50000
#define FDIM   256
#define KMIX   5

typedef unsigned long long ull;

// ---------------- scratch (static device allocations) ----------------
__device__ float g_S0[NNODES * FDIM];     // X0 + scatter-add of X0[src]
__device__ float g_SM[NNODES * FDIM];     // mask + scatter-add of mask[src]
__device__ float g_X0[NNODES * FDIM];     // x*(1-mask)  (gather source for edges)
__device__ unsigned g_mbits[NNODES * 8];  // bit-packed mask, 256 bits/node
__device__ float g_indeg[NNODES];
__device__ float g_gamma[NNODES * KMIX];
__device__ int   g_flags[2];              // [0]: mask is 1-byte?  [1]: edges int64?

// ---------------- f32x2 packed helpers ----------------
__device__ __forceinline__ ull pack2(float a, float b) {
    ull r; asm("mov.b64 %0, {%1, %2};" : "=l"(r) : "f"(a), "f"(b)); return r;
}
__device__ __forceinline__ ull dup2(float a) { return pack2(a, a); }
__device__ __forceinline__ ull mul2(ull a, ull b) {
    ull r; asm("mul.rn.f32x2 %0, %1, %2;" : "=l"(r) : "l"(a), "l"(b)); return r;
}
__device__ __forceinline__ void fma2(ull& d, ull a, ull b) {
    asm("fma.rn.f32x2 %0, %1, %2, %0;" : "+l"(d) : "l"(a), "l"(b));
}
__device__ __forceinline__ void unpack2(ull v, float& a, float& b) {
    asm("mov.b64 {%0, %1}, %2;" : "=f"(a), "=f"(b) : "l"(v));
}

// ---------------- dtype detection ----------------
__global__ void detect_kernel(const void* mask, const void* edges) {
    int t = threadIdx.x;
    int any_m = 0, any_e = 0;
    const unsigned char* mb = (const unsigned char*)mask;
    const int* ei = (const int*)edges;
    for (int i = t; i < 4096; i += 256) {
        if (mb[4 * i + 1] != 0) any_m = 1;   // bool bytes -> nonzero; int32 {0,1} byte1 == 0
        if (ei[2 * i + 1] != 0) any_e = 1;   // int64 high words == 0
    }
    any_m = __syncthreads_or(any_m);
    any_e = __syncthreads_or(any_e);
    if (t == 0) {
        g_flags[0] = any_m ? 1 : 0;
        g_flags[1] = any_e ? 0 : 1;
    }
}

// ---------------- fused prep: X0/S0/SM init + bitmask + gamma + indeg=0 ----
__global__ __launch_bounds__(256) void prep_kernel(
    const float* __restrict__ x, const void* __restrict__ mask,
    const float* __restrict__ logp, const float* __restrict__ means,
    const float* __restrict__ logvars)
{
    int n = blockIdx.x;
    int f = threadIdx.x;   // 256 threads = one node row
    int idx = n * FDIM + f;
    int m = g_flags[0] ? (int)((const unsigned char*)mask)[idx]
                       : ((const int*)mask)[idx];
    float xv = x[idx];
    float x0 = m ? 0.0f : xv;
    g_X0[idx] = x0;
    g_S0[idx] = x0;
    g_SM[idx] = m ? 1.0f : 0.0f;

    unsigned bal = __ballot_sync(0xffffffffu, m);
    int w = f >> 5, lane = f & 31;
    if (lane == 0) g_mbits[n * 8 + w] = bal;
    if (f == 0) g_indeg[n] = 0.0f;

    // gamma logits: -0.5 * sum_{unmasked f} (x-mean_k)^2 / var_k
    float q[KMIX];
#pragma unroll
    for (int k = 0; k < KMIX; k++) {
        float d = xv - means[k * FDIM + f];
        float iv = expf(-logvars[k * FDIM + f]);
        q[k] = m ? 0.0f : d * d * iv;
    }
#pragma unroll
    for (int k = 0; k < KMIX; k++)
        for (int off = 16; off; off >>= 1)
            q[k] += __shfl_down_sync(0xffffffffu, q[k], off);

    __shared__ float red[8][KMIX];
    if (lane == 0)
#pragma unroll
        for (int k = 0; k < KMIX; k++) red[w][k] = q[k];
    __syncthreads();
    if (f == 0) {
        float l[KMIX], mx = -1e30f;
#pragma unroll
        for (int k = 0; k < KMIX; k++) {
            float s = 0.f;
            for (int ww = 0; ww < 8; ww++) s += red[ww][k];
            l[k] = logp[k] - 0.5f * s;
            mx = fmaxf(mx, l[k]);
        }
        float e[KMIX], se = 0.f;
#pragma unroll
        for (int k = 0; k < KMIX; k++) { e[k] = expf(l[k] - mx); se += e[k]; }
        float inv = 1.0f / se;
#pragma unroll
        for (int k = 0; k < KMIX; k++) g_gamma[n * KMIX + k] = e[k] * inv;
    }
}

// ---------------- edge scatter-add (one warp per edge) ----------------
__device__ __forceinline__ void red4(float* p, float a, float b, float c, float d) {
    asm volatile("red.global.add.v4.f32 [%0], {%1,%2,%3,%4};"
                 :: "l"(p), "f"(a), "f"(b), "f"(c), "f"(d) : "memory");
}

__global__ __launch_bounds__(256) void edge_kernel(const void* __restrict__ edges, int E) {
    int gw = (blockIdx.x * blockDim.x + threadIdx.x) >> 5;
    int lane = threadIdx.x & 31;
    if (gw >= E) return;
    int src, dst;
    if (g_flags[1]) {
        const long long* e = (const long long*)edges;
        src = (int)e[gw]; dst = (int)e[E + gw];
    } else {
        const int* e = (const int*)edges;
        src = e[gw]; dst = e[E + gw];
    }
    const float4* xs = (const float4*)(g_X0 + (size_t)src * FDIM);
    float4 a0 = xs[lane];
    float4 a1 = xs[lane + 32];

    const unsigned* mb = g_mbits + src * 8;
    unsigned w0 = mb[lane >> 3];        // word for f = 4*lane..4*lane+3
    unsigned w1 = mb[4 + (lane >> 3)];  // word for f = 128+4*lane..
    int sh = (lane & 7) << 2;
    w0 >>= sh; w1 >>= sh;

    float* S0p = g_S0 + (size_t)dst * FDIM;
    float* SMp = g_SM + (size_t)dst * FDIM;

    // X0 already has the mask applied — S0 atomics need no predication
    red4(S0p + 4 * lane, a0.x, a0.y, a0.z, a0.w);
    red4(S0p + 128 + 4 * lane, a1.x, a1.y, a1.z, a1.w);
    red4(SMp + 4 * lane,
         (w0 & 1u) ? 1.f : 0.f, (w0 & 2u) ? 1.f : 0.f,
         (w0 & 4u) ? 1.f : 0.f, (w0 & 8u) ? 1.f : 0.f);
    red4(SMp + 128 + 4 * lane,
         (w1 & 1u) ? 1.f : 0.f, (w1 & 2u) ? 1.f : 0.f,
         (w1 & 4u) ? 1.f : 0.f, (w1 & 8u) ? 1.f : 0.f);
    if (lane == 0) atomicAdd(&g_indeg[dst], 1.0f);
}

// ---------------- fused GEMM (f32x2 packed) + ex_relu + mixture ----------
__device__ __forceinline__ float ex_relu(float mu, float s) {
    if (s <= 0.0f) return fmaxf(mu, 0.0f);
    float ss = sqrtf(s);
    float w  = mu / ss;
    return ss * (0.3989422804014327f * expf(-0.5f * w * w)
                 + 0.5f * w * (1.0f + erff(w * 0.7071067811865476f)));
}

#define GN 64
#define GO 32
#define GF 32

__global__ __launch_bounds__(256) void gemm_epi_kernel(
    const float* __restrict__ W, const float* __restrict__ bias,
    const float* __restrict__ means, const float* __restrict__ logvars,
    float* __restrict__ out)
{
    __shared__ float As0[GN][GF + 1];
    __shared__ float Asm[GN][GF + 1];
    __shared__ __align__(16) float Wsf[GF][GO];
    __shared__ ull msd[KMIX][GF];   // means duplicated into both f32x2 halves
    __shared__ ull vsd[KMIX][GF];   // variances duplicated

    int nb = blockIdx.x * GN;
    int ob = blockIdx.y * GO;
    int t  = threadIdx.x;
    int tx = t & 15;       // 16 out-pairs -> 32 outs (pair packed in f32x2)
    int ty = t >> 4;       // 16 node-quads -> 64 nodes

    ull t0[4] = {};        // lo = out o, hi = out o+1
    ull tm[KMIX][4] = {};
    ull tv[KMIX][4] = {};

    for (int ff = 0; ff < FDIM; ff += GF) {
#pragma unroll
        for (int j = 0; j < 2; j++) {
            int id = t + j * 256;
            int r = id >> 3;
            int c = (id & 7) << 2;
            int node = nb + r;
            float4 v0, vm;
            if (node < NNODES) {
                v0 = *(const float4*)&g_S0[(size_t)node * FDIM + ff + c];
                vm = *(const float4*)&g_SM[(size_t)node * FDIM + ff + c];
            } else {
                v0 = make_float4(0.f, 0.f, 0.f, 0.f);
                vm = v0;
            }
            As0[r][c] = v0.x; As0[r][c + 1] = v0.y; As0[r][c + 2] = v0.z; As0[r][c + 3] = v0.w;
            Asm[r][c] = vm.x; Asm[r][c + 1] = vm.y; Asm[r][c + 2] = vm.z; Asm[r][c + 3] = vm.w;
        }
        {
            int r = t >> 3;
            int c = (t & 7) << 2;
            float4 wv = *(const float4*)&W[(size_t)(ff + r) * FDIM + ob + c];
            *(float4*)&Wsf[r][c] = wv;
        }
        if (t < KMIX * GF) {
            int k = t >> 5, j = t & 31;
            msd[k][j] = dup2(means[k * FDIM + ff + j]);
            vsd[k][j] = dup2(expf(logvars[k * FDIM + ff + j]));
        }
        __syncthreads();

#pragma unroll 8
        for (int fj = 0; fj < GF; fj++) {
            ull wp = *(const ull*)&Wsf[fj][tx << 1];   // (w0, w1) packed
            ull w2 = mul2(wp, wp);
            ull wk[KMIX], wv[KMIX];
#pragma unroll
            for (int k = 0; k < KMIX; k++) {
                wk[k] = mul2(wp, msd[k][fj]);
                wv[k] = mul2(w2, vsd[k][fj]);
            }
            ull a0[4], am[4];
#pragma unroll
            for (int i = 0; i < 4; i++) {
                a0[i] = dup2(As0[(ty << 2) + i][fj]);
                am[i] = dup2(Asm[(ty << 2) + i][fj]);
            }
#pragma unroll
            for (int i = 0; i < 4; i++) fma2(t0[i], a0[i], wp);
#pragma unroll
            for (int k = 0; k < KMIX; k++)
#pragma unroll
                for (int i = 0; i < 4; i++) {
                    fma2(tm[k][i], am[i], wk[k]);
                    fma2(tv[k][i], am[i], wv[k]);
                }
        }
        __syncthreads();
    }

    // epilogue
#pragma unroll
    for (int i = 0; i < 4; i++) {
        int node = nb + (ty << 2) + i;
        if (node >= NNODES) continue;
        float deg1 = 1.0f + g_indeg[node];
        float g[KMIX];
#pragma unroll
        for (int k = 0; k < KMIX; k++) g[k] = g_gamma[node * KMIX + k];

        float base0, base1;
        unpack2(t0[i], base0, base1);
        int oo = ob + (tx << 1);
        float bb0 = bias[oo] * deg1;
        float bb1 = bias[oo + 1] * deg1;
        float acc0 = 0.f, acc1 = 0.f;
#pragma unroll
        for (int k = 0; k < KMIX; k++) {
            float m0, m1, v0, v1;
            unpack2(tm[k][i], m0, m1);
            unpack2(tv[k][i], v0, v1);
            acc0 += g[k] * ex_relu(base0 + m0 + bb0, v0);
            acc1 += g[k] * ex_relu(base1 + m1 + bb1, v1);
        }
        *(float2*)&out[(size_t)node * FDIM + oo] = make_float2(acc0, acc1);
    }
}

// ---------------- launcher ----------------
extern "C" void kernel_launch(void* const* d_in, const int* in_sizes, int n_in,
                              void* d_out, int out_size) {
    const float* x       = (const float*)d_in[0];
    const void*  edges   = d_in[1];
    const void*  mask    = d_in[2];
    const float* logp    = (const float*)d_in[3];
    const float* means   = (const float*)d_in[4];
    const float* logvars = (const float*)d_in[5];
    const float* W       = (const float*)d_in[6];
    const float* bias    = (const float*)d_in[7];
    float* out = (float*)d_out;

    int E = in_sizes[1] / 2;

    detect_kernel<<<1, 256>>>(mask, edges);
    prep_kernel<<<NNODES, 256>>>(x, mask, logp, means, logvars);

    int eblocks = (E * 32 + 255) / 256;
    edge_kernel<<<eblocks, 256>>>(edges, E);

    dim3 ggrid((NNODES + GN - 1) / GN, FDIM / GO);
    gemm_epi_kernel<<<ggrid, 256>>>(W, bias, means, logvars, out);
}

// round 4
// speedup vs baseline: 2.2048x; 1.9107x over previous
#include <cuda_runtime.h>
#include <cuda_bf16.h>
#include <cstdint>

#define NNODES 50000
#define FDIM   256
#define KMIX   5

// ---------------- scratch ----------------
__device__ float g_S0[NNODES * FDIM];         // fp32 accum: X0 + scatter
__device__ float g_X0[NNODES * FDIM];         // masked x (gather source)
__device__ unsigned g_SMb[NNODES * 64];       // packed u8 mask-counts (256 B/node)
__device__ unsigned g_mbits[NNODES * 8];      // bit mask
__device__ float g_indeg[NNODES];
__device__ float g_gamma[NNODES * KMIX];
__device__ int   g_flags[2];
__device__ __nv_bfloat16 g_S0h[NNODES * FDIM];
__device__ __nv_bfloat16 g_S0l[NNODES * FDIM];
__device__ __nv_bfloat16 g_SMh[NNODES * FDIM];
// B concat: [hi/lo][group g (32 outs)][352 rows (n)][256 (k)]
__device__ __nv_bfloat16 g_B[2][8][352 * 256];

// ---------------- PTX helpers (baseline ISA only, no sm_103a features) ----
__device__ __forceinline__ uint32_t smem_u32(const void* p) {
    uint32_t a;
    asm("{ .reg .u64 t; cvta.to.shared.u64 t, %1; cvt.u32.u64 %0, t; }" : "=r"(a) : "l"(p));
    return a;
}
__device__ __forceinline__ void cpasync16(uint32_t dst, const void* src) {
    asm volatile("cp.async.cg.shared.global [%0], [%1], 16;" :: "r"(dst), "l"(src));
}
#define CP_COMMIT() asm volatile("cp.async.commit_group;" ::: "memory")
#define CP_WAIT1()  asm volatile("cp.async.wait_group 1;" ::: "memory")
#define CP_WAIT0()  asm volatile("cp.async.wait_group 0;" ::: "memory")

__device__ __forceinline__ void ldsm4(uint32_t* r, uint32_t addr) {
    asm volatile("ldmatrix.sync.aligned.m8n8.x4.shared.b16 {%0,%1,%2,%3}, [%4];"
                 : "=r"(r[0]), "=r"(r[1]), "=r"(r[2]), "=r"(r[3]) : "r"(addr));
}
__device__ __forceinline__ void mma16816(float* d, const uint32_t* a, const uint32_t* b) {
    asm volatile("mma.sync.aligned.m16n8k16.row.col.f32.bf16.bf16.f32 "
                 "{%0,%1,%2,%3}, {%4,%5,%6,%7}, {%8,%9}, {%0,%1,%2,%3};"
                 : "+f"(d[0]), "+f"(d[1]), "+f"(d[2]), "+f"(d[3])
                 : "r"(a[0]), "r"(a[1]), "r"(a[2]), "r"(a[3]), "r"(b[0]), "r"(b[1]));
}

// ---------------- dtype detection ----------------
__global__ void detect_kernel(const void* mask, const void* edges) {
    int t = threadIdx.x;
    int any_m = 0, any_e = 0;
    const unsigned char* mb = (const unsigned char*)mask;
    const int* ei = (const int*)edges;
    for (int i = t; i < 4096; i += 256) {
        if (mb[4 * i + 1] != 0) any_m = 1;
        if (ei[2 * i + 1] != 0) any_e = 1;
    }
    any_m = __syncthreads_or(any_m);
    any_e = __syncthreads_or(any_e);
    if (t == 0) { g_flags[0] = any_m ? 1 : 0; g_flags[1] = any_e ? 0 : 1; }
}

// ---------------- prep: X0/S0/SMb/mbits + gamma + indeg ----------------
__global__ __launch_bounds__(256) void prep_kernel(
    const float* __restrict__ x, const void* __restrict__ mask,
    const float* __restrict__ logp, const float* __restrict__ means,
    const float* __restrict__ logvars)
{
    int n = blockIdx.x;
    int f = threadIdx.x;
    int idx = n * FDIM + f;
    int m = g_flags[0] ? (int)((const unsigned char*)mask)[idx]
                       : ((const int*)mask)[idx];
    float xv = x[idx];
    float x0 = m ? 0.0f : xv;
    g_X0[idx] = x0;
    g_S0[idx] = x0;

    unsigned bal = __ballot_sync(0xffffffffu, m);
    int w = f >> 5, lane = f & 31;
    if (lane == 0) g_mbits[n * 8 + w] = bal;
    if (lane < 8) {
        unsigned nib = (bal >> (lane * 4)) & 0xf;
        unsigned v = (nib & 1u) | ((nib & 2u) << 7) | ((nib & 4u) << 14) | ((nib & 8u) << 21);
        g_SMb[n * 64 + w * 8 + lane] = v;
    }
    if (f == 0) g_indeg[n] = 0.0f;

    float q[KMIX];
#pragma unroll
    for (int k = 0; k < KMIX; k++) {
        float d = xv - means[k * FDIM + f];
        float iv = expf(-logvars[k * FDIM + f]);
        q[k] = m ? 0.0f : d * d * iv;
    }
#pragma unroll
    for (int k = 0; k < KMIX; k++)
        for (int off = 16; off; off >>= 1)
            q[k] += __shfl_down_sync(0xffffffffu, q[k], off);

    __shared__ float red[8][KMIX];
    if (lane == 0)
#pragma unroll
        for (int k = 0; k < KMIX; k++) red[w][k] = q[k];
    __syncthreads();
    if (f == 0) {
        float l[KMIX], mx = -1e30f;
#pragma unroll
        for (int k = 0; k < KMIX; k++) {
            float s = 0.f;
            for (int ww = 0; ww < 8; ww++) s += red[ww][k];
            l[k] = logp[k] - 0.5f * s;
            mx = fmaxf(mx, l[k]);
        }
        float e[KMIX], se = 0.f;
#pragma unroll
        for (int k = 0; k < KMIX; k++) { e[k] = expf(l[k] - mx); se += e[k]; }
        float inv = 1.0f / se;
#pragma unroll
        for (int k = 0; k < KMIX; k++) g_gamma[n * KMIX + k] = e[k] * inv;
    }
}

// ---------------- edge scatter-add ----------------
__device__ __forceinline__ void red4(float* p, float a, float b, float c, float d) {
    asm volatile("red.global.add.v4.f32 [%0], {%1,%2,%3,%4};"
                 :: "l"(p), "f"(a), "f"(b), "f"(c), "f"(d) : "memory");
}
__device__ __forceinline__ void redu(unsigned* p, unsigned v) {
    asm volatile("red.global.add.u32 [%0], %1;" :: "l"(p), "r"(v) : "memory");
}

__global__ __launch_bounds__(256) void edge_kernel(const void* __restrict__ edges, int E) {
    int gw = (blockIdx.x * blockDim.x + threadIdx.x) >> 5;
    int lane = threadIdx.x & 31;
    if (gw >= E) return;
    int src, dst;
    if (g_flags[1]) {
        const long long* e = (const long long*)edges;
        src = (int)e[gw]; dst = (int)e[E + gw];
    } else {
        const int* e = (const int*)edges;
        src = e[gw]; dst = e[E + gw];
    }
    const float4* xs = (const float4*)(g_X0 + (size_t)src * FDIM);
    float4 a0 = xs[lane];
    float4 a1 = xs[lane + 32];

    unsigned m = g_mbits[src * 8 + (lane >> 2)];
    unsigned b = (m >> ((lane & 3) * 8)) & 0xffu;
    unsigned lo = b & 0xf, hi = (b >> 4) & 0xf;
    unsigned v0 = (lo & 1u) | ((lo & 2u) << 7) | ((lo & 4u) << 14) | ((lo & 8u) << 21);
    unsigned v1 = (hi & 1u) | ((hi & 2u) << 7) | ((hi & 4u) << 14) | ((hi & 8u) << 21);

    float* S0p = g_S0 + (size_t)dst * FDIM;
    red4(S0p + 4 * lane, a0.x, a0.y, a0.z, a0.w);
    red4(S0p + 128 + 4 * lane, a1.x, a1.y, a1.z, a1.w);
    {
        int fbase = 32 * (lane >> 2) + 8 * (lane & 3);
        unsigned* SMp = g_SMb + (size_t)dst * 64 + (fbase >> 2);
        redu(SMp, v0);
        redu(SMp + 1, v1);
    }
    if (lane == 0) atomicAdd(&g_indeg[dst], 1.0f);
}

// ---------------- convert: S0 -> bf16 hi/lo, SMb -> bf16 ----------------
__global__ __launch_bounds__(256) void convert_kernel() {
    int i = blockIdx.x * blockDim.x + threadIdx.x;
    float s0 = g_S0[i];
    __nv_bfloat16 h = __float2bfloat16_rn(s0);
    g_S0h[i] = h;
    g_S0l[i] = __float2bfloat16_rn(s0 - __bfloat162float(h));
    unsigned char c = ((const unsigned char*)g_SMb)[i];
    g_SMh[i] = __float2bfloat16_rn((float)c);
}

// ---------------- B precompute (n-concat, hi/lo split) ----------------
__global__ __launch_bounds__(256) void bprep_kernel(
    const float* __restrict__ W, const float* __restrict__ means,
    const float* __restrict__ logvars)
{
    int gidx = blockIdx.x;         // 8*352
    int g = gidx / 352, n = gidx % 352;
    int f = threadIdx.x;
    float val;
    if (n < 32) {
        int o = g * 32 + n;
        val = W[f * FDIM + o];
    } else {
        int mat = (n - 32) >> 5;
        int o = g * 32 + ((n - 32) & 31);
        int k = mat >> 1;
        float w = W[f * FDIM + o];
        if ((mat & 1) == 0) val = means[k * FDIM + f] * w;
        else                val = expf(logvars[k * FDIM + f]) * w * w;
    }
    __nv_bfloat16 h = __float2bfloat16_rn(val);
    g_B[0][g][n * FDIM + f] = h;
    g_B[1][g][n * FDIM + f] = __float2bfloat16_rn(val - __bfloat162float(h));
}

// ---------------- mma.sync GEMM + epilogue ----------------
__device__ __forceinline__ float ex_relu(float mu, float s) {
    if (s <= 0.0f) return fmaxf(mu, 0.0f);
    float ss = sqrtf(s);
    float w  = mu / ss;
    return ss * (0.3989422804014327f * expf(-0.5f * w * w)
                 + 0.5f * w * (1.0f + erff(w * 0.7071067811865476f)));
}

// SMEM layout (per buffer), 80-byte row pitch (conflict-free ldmatrix, gcd(5,8)=1)
#define OFF_A0H 0
#define OFF_A0L 5120
#define OFF_AMH 10240
#define OFF_BH  15360
#define OFF_BL  43520
#define BUFSZ   71680
#define SM_TOTAL (2 * BUFSZ)      // 143360

__device__ __forceinline__ void load_chunk(uint32_t sbuf, int nb, int g, int kc) {
    int t = threadIdx.x;
    // A tiles: S0h, S0l, SMh — 64 rows x 32 k (64B) each
    const char* srcA0 = (const char*)g_S0h;
    const char* srcA1 = (const char*)g_S0l;
    const char* srcA2 = (const char*)g_SMh;
#pragma unroll
    for (int j = 0; j < 3; j++) {
        int id = t + j * 256;                 // 768 total
        int tile = id >> 8, rem = id & 255;
        int row = rem >> 2, c16 = rem & 3;
        int node = nb + row; if (node >= NNODES) node = NNODES - 1;
        const char* base = tile == 0 ? srcA0 : (tile == 1 ? srcA1 : srcA2);
        const char* src = base + ((size_t)node * FDIM + kc * 32 + c16 * 8) * 2;
        uint32_t dst = sbuf + OFF_A0H + tile * 5120 + row * 80 + c16 * 16;
        cpasync16(dst, src);
    }
    // B tiles: hi + lo, 352 rows x 32 k
    const char* bh = (const char*)&g_B[0][g][0];
    const char* bl = (const char*)&g_B[1][g][0];
#pragma unroll
    for (int j = 0; j < 11; j++) {
        int id = t + j * 256;                 // 2816 total
        int h = id >= 1408; int rem = id - h * 1408;
        int row = rem >> 2, c16 = rem & 3;
        const char* src = (h ? bl : bh) + ((size_t)row * FDIM + kc * 32 + c16 * 8) * 2;
        uint32_t dst = sbuf + (h ? OFF_BL : OFF_BH) + row * 80 + c16 * 16;
        cpasync16(dst, src);
    }
}

__global__ __launch_bounds__(256) void gemm_mma_kernel(
    const float* __restrict__ bias, float* __restrict__ out)
{
    extern __shared__ char smem[];
    uint32_t sb = smem_u32(smem);
    int t = threadIdx.x;
    int lane = t & 31, wid = t >> 5;
    int wm = wid & 3, wn = wid >> 2;          // 4 m-tiles x 2 n-tiles
    int nb = blockIdx.x * 64;
    int g  = blockIdx.y;
    int ob = g * 32;

    float acc[11][8];
#pragma unroll
    for (int a = 0; a < 11; a++)
#pragma unroll
        for (int d = 0; d < 8; d++) acc[a][d] = 0.0f;

    load_chunk(sb, nb, g, 0);
    CP_COMMIT();

    // per-kstep ldmatrix address components
    int arow = wm * 16 + (lane & 15);
    int acolsel = (lane >> 4) << 3;                 // 0 or 8
    int brow = wn * 16 + (lane & 7) + ((lane >> 4) << 3);
    int bcolsel = ((lane >> 3) & 1) << 3;

    for (int c = 0; c < 8; c++) {
        if (c < 7) { load_chunk(sb + ((c + 1) & 1) * BUFSZ, nb, g, c + 1); CP_COMMIT(); CP_WAIT1(); }
        else CP_WAIT0();
        __syncthreads();

        uint32_t b32 = sb + (c & 1) * BUFSZ;
#pragma unroll
        for (int j = 0; j < 2; j++) {
            uint32_t aoff = (uint32_t)(arow * 80 + (j * 16 + acolsel) * 2);
            uint32_t aH[4], aL[4], aM[4];
            ldsm4(aH, b32 + OFF_A0H + aoff);
            ldsm4(aL, b32 + OFF_A0L + aoff);
            ldsm4(aM, b32 + OFF_AMH + aoff);

            uint32_t boff0 = (uint32_t)(brow * 80 + (j * 16 + bcolsel) * 2);
            uint32_t bh[4], bl[4];
            // t0 path (rows 0..31): S0h*Bh + S0h*Bl + S0l*Bh
            ldsm4(bh, b32 + OFF_BH + boff0);
            ldsm4(bl, b32 + OFF_BL + boff0);
            mma16816(&acc[0][0], aH, &bh[0]); mma16816(&acc[0][4], aH, &bh[2]);
            mma16816(&acc[0][0], aH, &bl[0]); mma16816(&acc[0][4], aH, &bl[2]);
            mma16816(&acc[0][0], aL, &bh[0]); mma16816(&acc[0][4], aL, &bh[2]);
            // SM path: SMh*(Bh+Bl), rows a*32..a*32+31
#pragma unroll
            for (int a = 1; a <= 10; a++) {
                uint32_t boff = boff0 + (uint32_t)(a * 32 * 80);
                ldsm4(bh, b32 + OFF_BH + boff);
                ldsm4(bl, b32 + OFF_BL + boff);
                mma16816(&acc[a][0], aM, &bh[0]); mma16816(&acc[a][4], aM, &bh[2]);
                mma16816(&acc[a][0], aM, &bl[0]); mma16816(&acc[a][4], aM, &bl[2]);
            }
        }
        __syncthreads();
    }

    // epilogue
    int r0 = lane >> 2, c0 = (lane & 3) * 2;
#pragma unroll
    for (int i = 0; i < 2; i++) {
        int node = nb + wm * 16 + r0 + i * 8;
        if (node >= NNODES) continue;
        float deg1 = 1.0f + g_indeg[node];
        float gam[KMIX];
#pragma unroll
        for (int k = 0; k < KMIX; k++) gam[k] = g_gamma[node * KMIX + k];
#pragma unroll
        for (int f = 0; f < 2; f++) {
            int o = ob + wn * 16 + f * 8 + c0;
            float bb0 = bias[o] * deg1;
            float bb1 = bias[o + 1] * deg1;
            int d = f * 4 + i * 2;
            float mu0 = acc[0][d], mu1 = acc[0][d + 1];
            float s0 = 0.f, s1 = 0.f;
#pragma unroll
            for (int k = 0; k < KMIX; k++) {
                s0 += gam[k] * ex_relu(mu0 + acc[1 + 2 * k][d] + bb0,     acc[2 + 2 * k][d]);
                s1 += gam[k] * ex_relu(mu1 + acc[1 + 2 * k][d + 1] + bb1, acc[2 + 2 * k][d + 1]);
            }
            *(float2*)&out[(size_t)node * FDIM + o] = make_float2(s0, s1);
        }
    }
}

// ---------------- launcher ----------------
extern "C" void kernel_launch(void* const* d_in, const int* in_sizes, int n_in,
                              void* d_out, int out_size) {
    const float* x       = (const float*)d_in[0];
    const void*  edges   = d_in[1];
    const void*  mask    = d_in[2];
    const float* logp    = (const float*)d_in[3];
    const float* means   = (const float*)d_in[4];
    const float* logvars = (const float*)d_in[5];
    const float* W       = (const float*)d_in[6];
    const float* bias    = (const float*)d_in[7];
    float* out = (float*)d_out;

    int E = in_sizes[1] / 2;

    cudaFuncSetAttribute(gemm_mma_kernel, cudaFuncAttributeMaxDynamicSharedMemorySize, SM_TOTAL);

    detect_kernel<<<1, 256>>>(mask, edges);
    prep_kernel<<<NNODES, 256>>>(x, mask, logp, means, logvars);

    int eblocks = (E * 32 + 255) / 256;
    edge_kernel<<<eblocks, 256>>>(edges, E);

    convert_kernel<<<(NNODES * FDIM) / 256, 256>>>();
    bprep_kernel<<<8 * 352, 256>>>(W, means, logvars);

    dim3 ggrid((NNODES + 63) / 64, 8);
    gemm_mma_kernel<<<ggrid, 256, SM_TOTAL>>>(bias, out);
}

// round 5
// speedup vs baseline: 2.3256x; 1.0548x over previous
#include <cuda_runtime.h>
#include <cuda_bf16.h>
#include <cstdint>

#define NNODES 50000
#define FDIM   256
#define KMIX   5
#define EMAX   1700000

// ---------------- scratch ----------------
__device__ unsigned g_mbits[NNODES * 8];      // bit mask, 256 bits/node
__device__ float g_indeg[NNODES];
__device__ float g_gamma[NNODES * KMIX];
__device__ int   g_flags[2];
__device__ int   g_count[NNODES];
__device__ int   g_cursor[NNODES];
__device__ int   g_offset[NNODES + 1];
__device__ int   g_sorted[EMAX];
__device__ __nv_bfloat16 g_S0h[NNODES * FDIM];
__device__ __nv_bfloat16 g_S0l[NNODES * FDIM];
__device__ __nv_bfloat16 g_SMh[NNODES * FDIM];
// B concat: [hi/lo][group g (32 outs)][352 rows (n)][256 (k)]
__device__ __nv_bfloat16 g_B[2][8][352 * 256];

// ---------------- PTX helpers (baseline ISA only) ----------------
__device__ __forceinline__ uint32_t smem_u32(const void* p) {
    uint32_t a;
    asm("{ .reg .u64 t; cvta.to.shared.u64 t, %1; cvt.u32.u64 %0, t; }" : "=r"(a) : "l"(p));
    return a;
}
__device__ __forceinline__ void cpasync16(uint32_t dst, const void* src) {
    asm volatile("cp.async.cg.shared.global [%0], [%1], 16;" :: "r"(dst), "l"(src));
}
#define CP_COMMIT() asm volatile("cp.async.commit_group;" ::: "memory")
#define CP_WAIT1()  asm volatile("cp.async.wait_group 1;" ::: "memory")
#define CP_WAIT0()  asm volatile("cp.async.wait_group 0;" ::: "memory")

__device__ __forceinline__ void ldsm4(uint32_t* r, uint32_t addr) {
    asm volatile("ldmatrix.sync.aligned.m8n8.x4.shared.b16 {%0,%1,%2,%3}, [%4];"
                 : "=r"(r[0]), "=r"(r[1]), "=r"(r[2]), "=r"(r[3]) : "r"(addr));
}
__device__ __forceinline__ void mma16816(float* d, const uint32_t* a, const uint32_t* b) {
    asm volatile("mma.sync.aligned.m16n8k16.row.col.f32.bf16.bf16.f32 "
                 "{%0,%1,%2,%3}, {%4,%5,%6,%7}, {%8,%9}, {%0,%1,%2,%3};"
                 : "+f"(d[0]), "+f"(d[1]), "+f"(d[2]), "+f"(d[3])
                 : "r"(a[0]), "r"(a[1]), "r"(a[2]), "r"(a[3]), "r"(b[0]), "r"(b[1]));
}

// ---------------- dtype detection + zero counters ----------------
__global__ void detect_kernel(const void* mask, const void* edges) {
    int t = threadIdx.x;
    int any_m = 0, any_e = 0;
    const unsigned char* mb = (const unsigned char*)mask;
    const int* ei = (const int*)edges;
    for (int i = t; i < 4096; i += 256) {
        if (mb[4 * i + 1] != 0) any_m = 1;
        if (ei[2 * i + 1] != 0) any_e = 1;
    }
    any_m = __syncthreads_or(any_m);
    any_e = __syncthreads_or(any_e);
    if (t == 0) { g_flags[0] = any_m ? 1 : 0; g_flags[1] = any_e ? 0 : 1; }
}

__global__ void zero_kernel() {
    int i = blockIdx.x * blockDim.x + threadIdx.x;
    if (i < NNODES) { g_count[i] = 0; g_cursor[i] = 0; }
}

// ---------------- prep: mbits + gamma ----------------
__global__ __launch_bounds__(256) void prep_kernel(
    const float* __restrict__ x, const void* __restrict__ mask,
    const float* __restrict__ logp, const float* __restrict__ means,
    const float* __restrict__ logvars)
{
    int n = blockIdx.x;
    int f = threadIdx.x;
    int idx = n * FDIM + f;
    int m = g_flags[0] ? (int)((const unsigned char*)mask)[idx]
                       : ((const int*)mask)[idx];
    float xv = x[idx];

    unsigned bal = __ballot_sync(0xffffffffu, m);
    int w = f >> 5, lane = f & 31;
    if (lane == 0) g_mbits[n * 8 + w] = bal;

    float q[KMIX];
#pragma unroll
    for (int k = 0; k < KMIX; k++) {
        float d = xv - means[k * FDIM + f];
        float iv = expf(-logvars[k * FDIM + f]);
        q[k] = m ? 0.0f : d * d * iv;
    }
#pragma unroll
    for (int k = 0; k < KMIX; k++)
        for (int off = 16; off; off >>= 1)
            q[k] += __shfl_down_sync(0xffffffffu, q[k], off);

    __shared__ float red[8][KMIX];
    if (lane == 0)
#pragma unroll
        for (int k = 0; k < KMIX; k++) red[w][k] = q[k];
    __syncthreads();
    if (f == 0) {
        float l[KMIX], mx = -1e30f;
#pragma unroll
        for (int k = 0; k < KMIX; k++) {
            float s = 0.f;
            for (int ww = 0; ww < 8; ww++) s += red[ww][k];
            l[k] = logp[k] - 0.5f * s;
            mx = fmaxf(mx, l[k]);
        }
        float e[KMIX], se = 0.f;
#pragma unroll
        for (int k = 0; k < KMIX; k++) { e[k] = expf(l[k] - mx); se += e[k]; }
        float inv = 1.0f / se;
#pragma unroll
        for (int k = 0; k < KMIX; k++) g_gamma[n * KMIX + k] = e[k] * inv;
    }
}

// ---------------- CSR build ----------------
__global__ void count_kernel(const void* __restrict__ edges, int E) {
    int i = blockIdx.x * blockDim.x + threadIdx.x;
    if (i >= E) return;
    int dst = g_flags[1] ? (int)((const long long*)edges)[E + i]
                         : ((const int*)edges)[E + i];
    atomicAdd(&g_count[dst], 1);
}

__global__ __launch_bounds__(1024) void scan_kernel() {
    const int SEG = (NNODES + 1023) / 1024;    // 49
    int t = threadIdx.x;
    int base = t * SEG;
    int s = 0;
    for (int i = 0; i < SEG; i++) {
        int idx = base + i;
        if (idx < NNODES) s += g_count[idx];
    }
    __shared__ int ss[1024];
    ss[t] = s;
    __syncthreads();
    for (int off = 1; off < 1024; off <<= 1) {
        int v = (t >= off) ? ss[t - off] : 0;
        __syncthreads();
        ss[t] += v;
        __syncthreads();
    }
    int run = ss[t] - s;   // exclusive
    for (int i = 0; i < SEG; i++) {
        int idx = base + i;
        if (idx < NNODES) { g_offset[idx] = run; run += g_count[idx]; }
    }
    if (t == 1023) g_offset[NNODES] = ss[1023];
}

__global__ void scatter_kernel(const void* __restrict__ edges, int E) {
    int i = blockIdx.x * blockDim.x + threadIdx.x;
    if (i >= E) return;
    int src, dst;
    if (g_flags[1]) {
        const long long* e = (const long long*)edges;
        src = (int)e[i]; dst = (int)e[E + i];
    } else {
        const int* e = (const int*)edges;
        src = e[i]; dst = e[E + i];
    }
    int pos = atomicAdd(&g_cursor[dst], 1);
    g_sorted[g_offset[dst] + pos] = src;
}

// ---------------- aggregate: CSR gather -> S0h/S0l/SMh + indeg ----------
__global__ __launch_bounds__(256) void aggregate_kernel(const float* __restrict__ x) {
    int n = blockIdx.x;
    int f = threadIdx.x;
    int wsel = f >> 5, bsel = f & 31;

    int beg = g_offset[n], end = g_offset[n + 1];

    // self term
    unsigned mb = g_mbits[n * 8 + wsel];
    int bit = (mb >> bsel) & 1;
    float xv = __ldg(&x[(size_t)n * FDIM + f]);
    float accS = bit ? 0.0f : xv;
    int cnt = bit;

    __shared__ int ssrc[256];
    for (int chunk = beg; chunk < end; chunk += 256) {
        int nload = min(256, end - chunk);
        __syncthreads();
        if (f < nload) ssrc[f] = g_sorted[chunk + f];
        __syncthreads();
        int i = 0;
        for (; i + 2 <= nload; i += 2) {
            int s0 = ssrc[i], s1 = ssrc[i + 1];
            unsigned m0 = __ldg(&g_mbits[s0 * 8 + wsel]);
            unsigned m1 = __ldg(&g_mbits[s1 * 8 + wsel]);
            float v0 = __ldg(&x[(size_t)s0 * FDIM + f]);
            float v1 = __ldg(&x[(size_t)s1 * FDIM + f]);
            int b0 = (m0 >> bsel) & 1, b1 = (m1 >> bsel) & 1;
            accS += b0 ? 0.0f : v0;
            accS += b1 ? 0.0f : v1;
            cnt += b0 + b1;
        }
        if (i < nload) {
            int s0 = ssrc[i];
            unsigned m0 = __ldg(&g_mbits[s0 * 8 + wsel]);
            float v0 = __ldg(&x[(size_t)s0 * FDIM + f]);
            int b0 = (m0 >> bsel) & 1;
            accS += b0 ? 0.0f : v0;
            cnt += b0;
        }
    }

    int idx = n * FDIM + f;
    __nv_bfloat16 h = __float2bfloat16_rn(accS);
    g_S0h[idx] = h;
    g_S0l[idx] = __float2bfloat16_rn(accS - __bfloat162float(h));
    g_SMh[idx] = __float2bfloat16_rn((float)cnt);
    if (f == 0) g_indeg[n] = (float)(end - beg);
}

// ---------------- B precompute (n-concat, hi/lo split) ----------------
__global__ __launch_bounds__(256) void bprep_kernel(
    const float* __restrict__ W, const float* __restrict__ means,
    const float* __restrict__ logvars)
{
    int gidx = blockIdx.x;         // 8*352
    int g = gidx / 352, n = gidx % 352;
    int f = threadIdx.x;
    float val;
    if (n < 32) {
        int o = g * 32 + n;
        val = W[f * FDIM + o];
    } else {
        int mat = (n - 32) >> 5;
        int o = g * 32 + ((n - 32) & 31);
        int k = mat >> 1;
        float w = W[f * FDIM + o];
        if ((mat & 1) == 0) val = means[k * FDIM + f] * w;
        else                val = expf(logvars[k * FDIM + f]) * w * w;
    }
    __nv_bfloat16 h = __float2bfloat16_rn(val);
    g_B[0][g][n * FDIM + f] = h;
    g_B[1][g][n * FDIM + f] = __float2bfloat16_rn(val - __bfloat162float(h));
}

// ---------------- mma.sync GEMM + epilogue ----------------
__device__ __forceinline__ float ex_relu(float mu, float s) {
    if (s <= 0.0f) return fmaxf(mu, 0.0f);
    float ss = sqrtf(s);
    float w  = mu / ss;
    return ss * (0.3989422804014327f * expf(-0.5f * w * w)
                 + 0.5f * w * (1.0f + erff(w * 0.7071067811865476f)));
}

// SMEM layout (per buffer), 80-byte row pitch (conflict-free ldmatrix)
#define OFF_A0H 0
#define OFF_A0L 5120
#define OFF_AMH 10240
#define OFF_BH  15360
#define OFF_BL  43520
#define BUFSZ   71680
#define SM_TOTAL (2 * BUFSZ)      // 143360

__device__ __forceinline__ void load_chunk(uint32_t sbuf, int nb, int g, int kc) {
    int t = threadIdx.x;
    const char* srcA0 = (const char*)g_S0h;
    const char* srcA1 = (const char*)g_S0l;
    const char* srcA2 = (const char*)g_SMh;
#pragma unroll
    for (int j = 0; j < 3; j++) {
        int id = t + j * 256;                 // 768 total
        int tile = id >> 8, rem = id & 255;
        int row = rem >> 2, c16 = rem & 3;
        int node = nb + row; if (node >= NNODES) node = NNODES - 1;
        const char* base = tile == 0 ? srcA0 : (tile == 1 ? srcA1 : srcA2);
        const char* src = base + ((size_t)node * FDIM + kc * 32 + c16 * 8) * 2;
        uint32_t dst = sbuf + OFF_A0H + tile * 5120 + row * 80 + c16 * 16;
        cpasync16(dst, src);
    }
    const char* bh = (const char*)&g_B[0][g][0];
    const char* bl = (const char*)&g_B[1][g][0];
#pragma unroll
    for (int j = 0; j < 11; j++) {
        int id = t + j * 256;                 // 2816 total
        int h = id >= 1408; int rem = id - h * 1408;
        int row = rem >> 2, c16 = rem & 3;
        const char* src = (h ? bl : bh) + ((size_t)row * FDIM + kc * 32 + c16 * 8) * 2;
        uint32_t dst = sbuf + (h ? OFF_BL : OFF_BH) + row * 80 + c16 * 16;
        cpasync16(dst, src);
    }
}

__global__ __launch_bounds__(256) void gemm_mma_kernel(
    const float* __restrict__ bias, float* __restrict__ out)
{
    extern __shared__ char smem[];
    uint32_t sb = smem_u32(smem);
    int t = threadIdx.x;
    int lane = t & 31, wid = t >> 5;
    int wm = wid & 3, wn = wid >> 2;          // 4 m-tiles x 2 n-tiles
    int nb = blockIdx.y * 64;                 // node tile (y!)
    int g  = blockIdx.x;                      // group   (x!) — A reuse in-wave
    int ob = g * 32;

    float acc[11][8];
#pragma unroll
    for (int a = 0; a < 11; a++)
#pragma unroll
        for (int d = 0; d < 8; d++) acc[a][d] = 0.0f;

    load_chunk(sb, nb, g, 0);
    CP_COMMIT();

    int arow = wm * 16 + (lane & 15);
    int acolsel = (lane >> 4) << 3;
    int brow = wn * 16 + (lane & 7) + ((lane >> 4) << 3);
    int bcolsel = ((lane >> 3) & 1) << 3;

    for (int c = 0; c < 8; c++) {
        if (c < 7) { load_chunk(sb + ((c + 1) & 1) * BUFSZ, nb, g, c + 1); CP_COMMIT(); CP_WAIT1(); }
        else CP_WAIT0();
        __syncthreads();

        uint32_t b32 = sb + (c & 1) * BUFSZ;
#pragma unroll
        for (int j = 0; j < 2; j++) {
            uint32_t aoff = (uint32_t)(arow * 80 + (j * 16 + acolsel) * 2);
            uint32_t aH[4], aL[4], aM[4];
            ldsm4(aH, b32 + OFF_A0H + aoff);
            ldsm4(aL, b32 + OFF_A0L + aoff);
            ldsm4(aM, b32 + OFF_AMH + aoff);

            uint32_t boff0 = (uint32_t)(brow * 80 + (j * 16 + bcolsel) * 2);
            uint32_t bh[4], bl[4];
            ldsm4(bh, b32 + OFF_BH + boff0);
            ldsm4(bl, b32 + OFF_BL + boff0);
            mma16816(&acc[0][0], aH, &bh[0]); mma16816(&acc[0][4], aH, &bh[2]);
            mma16816(&acc[0][0], aH, &bl[0]); mma16816(&acc[0][4], aH, &bl[2]);
            mma16816(&acc[0][0], aL, &bh[0]); mma16816(&acc[0][4], aL, &bh[2]);
#pragma unroll
            for (int a = 1; a <= 10; a++) {
                uint32_t boff = boff0 + (uint32_t)(a * 32 * 80);
                ldsm4(bh, b32 + OFF_BH + boff);
                ldsm4(bl, b32 + OFF_BL + boff);
                mma16816(&acc[a][0], aM, &bh[0]); mma16816(&acc[a][4], aM, &bh[2]);
                mma16816(&acc[a][0], aM, &bl[0]); mma16816(&acc[a][4], aM, &bl[2]);
            }
        }
        __syncthreads();
    }

    int r0 = lane >> 2, c0 = (lane & 3) * 2;
#pragma unroll
    for (int i = 0; i < 2; i++) {
        int node = nb + wm * 16 + r0 + i * 8;
        if (node >= NNODES) continue;
        float deg1 = 1.0f + g_indeg[node];
        float gam[KMIX];
#pragma unroll
        for (int k = 0; k < KMIX; k++) gam[k] = g_gamma[node * KMIX + k];
#pragma unroll
        for (int f = 0; f < 2; f++) {
            int o = ob + wn * 16 + f * 8 + c0;
            float bb0 = bias[o] * deg1;
            float bb1 = bias[o + 1] * deg1;
            int d = f * 4 + i * 2;
            float mu0 = acc[0][d], mu1 = acc[0][d + 1];
            float s0 = 0.f, s1 = 0.f;
#pragma unroll
            for (int k = 0; k < KMIX; k++) {
                s0 += gam[k] * ex_relu(mu0 + acc[1 + 2 * k][d] + bb0,     acc[2 + 2 * k][d]);
                s1 += gam[k] * ex_relu(mu1 + acc[1 + 2 * k][d + 1] + bb1, acc[2 + 2 * k][d + 1]);
            }
            *(float2*)&out[(size_t)node * FDIM + o] = make_float2(s0, s1);
        }
    }
}

// ---------------- launcher ----------------
extern "C" void kernel_launch(void* const* d_in, const int* in_sizes, int n_in,
                              void* d_out, int out_size) {
    const float* x       = (const float*)d_in[0];
    const void*  edges   = d_in[1];
    const void*  mask    = d_in[2];
    const float* logp    = (const float*)d_in[3];
    const float* means   = (const float*)d_in[4];
    const float* logvars = (const float*)d_in[5];
    const float* W       = (const float*)d_in[6];
    const float* bias    = (const float*)d_in[7];
    float* out = (float*)d_out;

    int E = in_sizes[1] / 2;

    cudaFuncSetAttribute(gemm_mma_kernel, cudaFuncAttributeMaxDynamicSharedMemorySize, SM_TOTAL);

    detect_kernel<<<1, 256>>>(mask, edges);
    zero_kernel<<<(NNODES + 255) / 256, 256>>>();
    prep_kernel<<<NNODES, 256>>>(x, mask, logp, means, logvars);

    int eb = (E + 255) / 256;
    count_kernel<<<eb, 256>>>(edges, E);
    scan_kernel<<<1, 1024>>>();
    scatter_kernel<<<eb, 256>>>(edges, E);
    aggregate_kernel<<<NNODES, 256>>>(x);

    bprep_kernel<<<8 * 352, 256>>>(W, means, logvars);

    dim3 ggrid(8, (NNODES + 63) / 64);
    gemm_mma_kernel<<<ggrid, 256, SM_TOTAL>>>(bias, out);
}

// round 6
// speedup vs baseline: 3.4917x; 1.5014x over previous
#include <cuda_runtime.h>
#include <cuda_fp16.h>
#include <cstdint>

#define NNODES 50000
#define FDIM   256
#define KMIX   5
#define EMAX   1700000

// ---------------- scratch ----------------
__device__ unsigned g_mbits[NNODES * 8];      // bit mask, 256 bits/node
__device__ float g_indeg[NNODES];
__device__ float g_gamma[NNODES * KMIX];
__device__ int   g_flags[2];
__device__ int   g_count[NNODES];
__device__ int   g_cursor[NNODES];
__device__ int   g_offset[NNODES + 1];
__device__ int   g_sorted[EMAX];
__device__ __half g_S0h[NNODES * FDIM];       // fp16 hi of aggregated S0
__device__ __half g_S0l[NNODES * FDIM];       // fp16 lo residual
__device__ __half g_SMh[NNODES * FDIM];       // aggregated mask counts (exact fp16)
// B concat (single fp16): [group g (32 outs)][352 rows (n)][256 (k)]
__device__ __half g_B[8][352 * 256];

// ---------------- PTX helpers (baseline ISA only) ----------------
__device__ __forceinline__ uint32_t smem_u32(const void* p) {
    uint32_t a;
    asm("{ .reg .u64 t; cvta.to.shared.u64 t, %1; cvt.u32.u64 %0, t; }" : "=r"(a) : "l"(p));
    return a;
}
__device__ __forceinline__ void cpasync16(uint32_t dst, const void* src) {
    asm volatile("cp.async.cg.shared.global [%0], [%1], 16;" :: "r"(dst), "l"(src));
}
#define CP_COMMIT() asm volatile("cp.async.commit_group;" ::: "memory")
#define CP_WAIT1()  asm volatile("cp.async.wait_group 1;" ::: "memory")
#define CP_WAIT0()  asm volatile("cp.async.wait_group 0;" ::: "memory")

__device__ __forceinline__ void ldsm4(uint32_t* r, uint32_t addr) {
    asm volatile("ldmatrix.sync.aligned.m8n8.x4.shared.b16 {%0,%1,%2,%3}, [%4];"
                 : "=r"(r[0]), "=r"(r[1]), "=r"(r[2]), "=r"(r[3]) : "r"(addr));
}
__device__ __forceinline__ void mma16816(float* d, const uint32_t* a, const uint32_t* b) {
    asm volatile("mma.sync.aligned.m16n8k16.row.col.f32.f16.f16.f32 "
                 "{%0,%1,%2,%3}, {%4,%5,%6,%7}, {%8,%9}, {%0,%1,%2,%3};"
                 : "+f"(d[0]), "+f"(d[1]), "+f"(d[2]), "+f"(d[3])
                 : "r"(a[0]), "r"(a[1]), "r"(a[2]), "r"(a[3]), "r"(b[0]), "r"(b[1]));
}

// ---------------- dtype detection + zero counters ----------------
__global__ void detect_kernel(const void* mask, const void* edges) {
    int t = threadIdx.x;
    int any_m = 0, any_e = 0;
    const unsigned char* mb = (const unsigned char*)mask;
    const int* ei = (const int*)edges;
    for (int i = t; i < 4096; i += 256) {
        if (mb[4 * i + 1] != 0) any_m = 1;
        if (ei[2 * i + 1] != 0) any_e = 1;
    }
    any_m = __syncthreads_or(any_m);
    any_e = __syncthreads_or(any_e);
    if (t == 0) { g_flags[0] = any_m ? 1 : 0; g_flags[1] = any_e ? 0 : 1; }
}

__global__ void zero_kernel() {
    int i = blockIdx.x * blockDim.x + threadIdx.x;
    if (i < NNODES) { g_count[i] = 0; g_cursor[i] = 0; }
}

// ---------------- prep: mbits + gamma ----------------
__global__ __launch_bounds__(256) void prep_kernel(
    const float* __restrict__ x, const void* __restrict__ mask,
    const float* __restrict__ logp, const float* __restrict__ means,
    const float* __restrict__ logvars)
{
    int n = blockIdx.x;
    int f = threadIdx.x;
    int idx = n * FDIM + f;
    int m = g_flags[0] ? (int)((const unsigned char*)mask)[idx]
                       : ((const int*)mask)[idx];
    float xv = x[idx];

    unsigned bal = __ballot_sync(0xffffffffu, m);
    int w = f >> 5, lane = f & 31;
    if (lane == 0) g_mbits[n * 8 + w] = bal;

    float q[KMIX];
#pragma unroll
    for (int k = 0; k < KMIX; k++) {
        float d = xv - means[k * FDIM + f];
        float iv = expf(-logvars[k * FDIM + f]);
        q[k] = m ? 0.0f : d * d * iv;
    }
#pragma unroll
    for (int k = 0; k < KMIX; k++)
        for (int off = 16; off; off >>= 1)
            q[k] += __shfl_down_sync(0xffffffffu, q[k], off);

    __shared__ float red[8][KMIX];
    if (lane == 0)
#pragma unroll
        for (int k = 0; k < KMIX; k++) red[w][k] = q[k];
    __syncthreads();
    if (f == 0) {
        float l[KMIX], mx = -1e30f;
#pragma unroll
        for (int k = 0; k < KMIX; k++) {
            float s = 0.f;
            for (int ww = 0; ww < 8; ww++) s += red[ww][k];
            l[k] = logp[k] - 0.5f * s;
            mx = fmaxf(mx, l[k]);
        }
        float e[KMIX], se = 0.f;
#pragma unroll
        for (int k = 0; k < KMIX; k++) { e[k] = expf(l[k] - mx); se += e[k]; }
        float inv = 1.0f / se;
#pragma unroll
        for (int k = 0; k < KMIX; k++) g_gamma[n * KMIX + k] = e[k] * inv;
    }
}

// ---------------- CSR build ----------------
__global__ void count_kernel(const void* __restrict__ edges, int E) {
    int i = blockIdx.x * blockDim.x + threadIdx.x;
    if (i >= E) return;
    int dst = g_flags[1] ? (int)((const long long*)edges)[E + i]
                         : ((const int*)edges)[E + i];
    atomicAdd(&g_count[dst], 1);
}

__global__ __launch_bounds__(1024) void scan_kernel() {
    const int SEG = (NNODES + 1023) / 1024;
    int t = threadIdx.x;
    int base = t * SEG;
    int s = 0;
    for (int i = 0; i < SEG; i++) {
        int idx = base + i;
        if (idx < NNODES) s += g_count[idx];
    }
    __shared__ int ss[1024];
    ss[t] = s;
    __syncthreads();
    for (int off = 1; off < 1024; off <<= 1) {
        int v = (t >= off) ? ss[t - off] : 0;
        __syncthreads();
        ss[t] += v;
        __syncthreads();
    }
    int run = ss[t] - s;
    for (int i = 0; i < SEG; i++) {
        int idx = base + i;
        if (idx < NNODES) { g_offset[idx] = run; run += g_count[idx]; }
    }
    if (t == 1023) g_offset[NNODES] = ss[1023];
}

__global__ void scatter_kernel(const void* __restrict__ edges, int E) {
    int i = blockIdx.x * blockDim.x + threadIdx.x;
    if (i >= E) return;
    int src, dst;
    if (g_flags[1]) {
        const long long* e = (const long long*)edges;
        src = (int)e[i]; dst = (int)e[E + i];
    } else {
        const int* e = (const int*)edges;
        src = e[i]; dst = e[E + i];
    }
    int pos = atomicAdd(&g_cursor[dst], 1);
    g_sorted[g_offset[dst] + pos] = src;
}

// ---------------- aggregate: CSR gather -> S0h/S0l/SMh + indeg ----------
__global__ __launch_bounds__(256) void aggregate_kernel(const float* __restrict__ x) {
    int n = blockIdx.x;
    int f = threadIdx.x;
    int wsel = f >> 5, bsel = f & 31;

    int beg = g_offset[n], end = g_offset[n + 1];

    unsigned mb = g_mbits[n * 8 + wsel];
    int bit = (mb >> bsel) & 1;
    float xv = __ldg(&x[(size_t)n * FDIM + f]);
    float accS = bit ? 0.0f : xv;
    int cnt = bit;

    __shared__ int ssrc[256];
    for (int chunk = beg; chunk < end; chunk += 256) {
        int nload = min(256, end - chunk);
        __syncthreads();
        if (f < nload) ssrc[f] = g_sorted[chunk + f];
        __syncthreads();
        int i = 0;
        for (; i + 2 <= nload; i += 2) {
            int s0 = ssrc[i], s1 = ssrc[i + 1];
            unsigned m0 = __ldg(&g_mbits[s0 * 8 + wsel]);
            unsigned m1 = __ldg(&g_mbits[s1 * 8 + wsel]);
            float v0 = __ldg(&x[(size_t)s0 * FDIM + f]);
            float v1 = __ldg(&x[(size_t)s1 * FDIM + f]);
            int b0 = (m0 >> bsel) & 1, b1 = (m1 >> bsel) & 1;
            accS += b0 ? 0.0f : v0;
            accS += b1 ? 0.0f : v1;
            cnt += b0 + b1;
        }
        if (i < nload) {
            int s0 = ssrc[i];
            unsigned m0 = __ldg(&g_mbits[s0 * 8 + wsel]);
            float v0 = __ldg(&x[(size_t)s0 * FDIM + f]);
            int b0 = (m0 >> bsel) & 1;
            accS += b0 ? 0.0f : v0;
            cnt += b0;
        }
    }

    int idx = n * FDIM + f;
    __half h = __float2half_rn(accS);
    g_S0h[idx] = h;
    g_S0l[idx] = __float2half_rn(accS - __half2float(h));
    g_SMh[idx] = __float2half_rn((float)cnt);
    if (f == 0) g_indeg[n] = (float)(end - beg);
}

// ---------------- B precompute (n-concat, single fp16) ----------------
__global__ __launch_bounds__(256) void bprep_kernel(
    const float* __restrict__ W, const float* __restrict__ means,
    const float* __restrict__ logvars)
{
    int gidx = blockIdx.x;         // 8*352
    int g = gidx / 352, n = gidx % 352;
    int f = threadIdx.x;
    float val;
    if (n < 32) {
        int o = g * 32 + n;
        val = W[f * FDIM + o];
    } else {
        int mat = (n - 32) >> 5;
        int o = g * 32 + ((n - 32) & 31);
        int k = mat >> 1;
        float w = W[f * FDIM + o];
        if ((mat & 1) == 0) val = means[k * FDIM + f] * w;
        else                val = expf(logvars[k * FDIM + f]) * w * w;
    }
    g_B[g][n * FDIM + f] = __float2half_rn(val);
}

// ---------------- mma.sync GEMM + epilogue ----------------
__device__ __forceinline__ float ex_relu(float mu, float s) {
    if (s <= 0.0f) return fmaxf(mu, 0.0f);
    float ss = sqrtf(s);
    float w  = mu / ss;
    return ss * (0.3989422804014327f * expf(-0.5f * w * w)
                 + 0.5f * w * (1.0f + erff(w * 0.7071067811865476f)));
}

// SMEM layout (per buffer), 80-byte row pitch (conflict-free ldmatrix)
#define OFF_A0H 0
#define OFF_A0L 5120
#define OFF_AMH 10240
#define OFF_B   15360
#define BUFSZ   43520
#define SM_TOTAL (2 * BUFSZ)      // 87040

__device__ __forceinline__ void load_chunk(uint32_t sbuf, int nb, int g, int kc) {
    int t = threadIdx.x;
    const char* srcA0 = (const char*)g_S0h;
    const char* srcA1 = (const char*)g_S0l;
    const char* srcA2 = (const char*)g_SMh;
#pragma unroll
    for (int j = 0; j < 3; j++) {
        int id = t + j * 256;                 // 768 total
        int tile = id >> 8, rem = id & 255;
        int row = rem >> 2, c16 = rem & 3;
        int node = nb + row; if (node >= NNODES) node = NNODES - 1;
        const char* base = tile == 0 ? srcA0 : (tile == 1 ? srcA1 : srcA2);
        const char* src = base + ((size_t)node * FDIM + kc * 32 + c16 * 8) * 2;
        uint32_t dst = sbuf + OFF_A0H + tile * 5120 + row * 80 + c16 * 16;
        cpasync16(dst, src);
    }
    const char* bp = (const char*)&g_B[g][0];
#pragma unroll
    for (int j = 0; j < 6; j++) {
        int id = t + j * 256;                 // 1408 total
        if (id < 1408) {
            int row = id >> 2, c16 = id & 3;
            const char* src = bp + ((size_t)row * FDIM + kc * 32 + c16 * 8) * 2;
            uint32_t dst = sbuf + OFF_B + row * 80 + c16 * 16;
            cpasync16(dst, src);
        }
    }
}

__global__ __launch_bounds__(256, 2) void gemm_mma_kernel(
    const float* __restrict__ bias, float* __restrict__ out)
{
    extern __shared__ char smem[];
    uint32_t sb = smem_u32(smem);
    int t = threadIdx.x;
    int lane = t & 31, wid = t >> 5;
    int wm = wid & 3, wn = wid >> 2;          // 4 m-tiles x 2 n-tiles
    int nb = blockIdx.y * 64;                 // node tile
    int g  = blockIdx.x;                      // group — A reuse in-wave
    int ob = g * 32;

    float acc[11][8];
#pragma unroll
    for (int a = 0; a < 11; a++)
#pragma unroll
        for (int d = 0; d < 8; d++) acc[a][d] = 0.0f;

    load_chunk(sb, nb, g, 0);
    CP_COMMIT();

    int arow = wm * 16 + (lane & 15);
    int acolsel = (lane >> 4) << 3;
    int brow = wn * 16 + (lane & 7) + ((lane >> 4) << 3);
    int bcolsel = ((lane >> 3) & 1) << 3;

    for (int c = 0; c < 8; c++) {
        if (c < 7) { load_chunk(sb + ((c + 1) & 1) * BUFSZ, nb, g, c + 1); CP_COMMIT(); CP_WAIT1(); }
        else CP_WAIT0();
        __syncthreads();

        uint32_t b32 = sb + (c & 1) * BUFSZ;
#pragma unroll
        for (int j = 0; j < 2; j++) {
            uint32_t aoff = (uint32_t)(arow * 80 + (j * 16 + acolsel) * 2);
            uint32_t aH[4], aL[4], aM[4];
            ldsm4(aH, b32 + OFF_A0H + aoff);
            ldsm4(aL, b32 + OFF_A0L + aoff);
            ldsm4(aM, b32 + OFF_AMH + aoff);

            uint32_t boff0 = (uint32_t)(brow * 80 + (j * 16 + bcolsel) * 2);
            uint32_t bq[4];
            // t0 path: (S0h + S0l) * B
            ldsm4(bq, b32 + OFF_B + boff0);
            mma16816(&acc[0][0], aH, &bq[0]); mma16816(&acc[0][4], aH, &bq[2]);
            mma16816(&acc[0][0], aL, &bq[0]); mma16816(&acc[0][4], aL, &bq[2]);
            // SM path: counts * B  (counts exact in fp16)
#pragma unroll
            for (int a = 1; a <= 10; a++) {
                uint32_t boff = boff0 + (uint32_t)(a * 32 * 80);
                ldsm4(bq, b32 + OFF_B + boff);
                mma16816(&acc[a][0], aM, &bq[0]); mma16816(&acc[a][4], aM, &bq[2]);
            }
        }
        __syncthreads();
    }

    int r0 = lane >> 2, c0 = (lane & 3) * 2;
#pragma unroll
    for (int i = 0; i < 2; i++) {
        int node = nb + wm * 16 + r0 + i * 8;
        if (node >= NNODES) continue;
        float deg1 = 1.0f + g_indeg[node];
        float gam[KMIX];
#pragma unroll
        for (int k = 0; k < KMIX; k++) gam[k] = g_gamma[node * KMIX + k];
#pragma unroll
        for (int f = 0; f < 2; f++) {
            int o = ob + wn * 16 + f * 8 + c0;
            float bb0 = bias[o] * deg1;
            float bb1 = bias[o + 1] * deg1;
            int d = f * 4 + i * 2;
            float mu0 = acc[0][d], mu1 = acc[0][d + 1];
            float s0 = 0.f, s1 = 0.f;
#pragma unroll
            for (int k = 0; k < KMIX; k++) {
                s0 += gam[k] * ex_relu(mu0 + acc[1 + 2 * k][d] + bb0,     acc[2 + 2 * k][d]);
                s1 += gam[k] * ex_relu(mu1 + acc[1 + 2 * k][d + 1] + bb1, acc[2 + 2 * k][d + 1]);
            }
            *(float2*)&out[(size_t)node * FDIM + o] = make_float2(s0, s1);
        }
    }
}

// ---------------- launcher ----------------
extern "C" void kernel_launch(void* const* d_in, const int* in_sizes, int n_in,
                              void* d_out, int out_size) {
    const float* x       = (const float*)d_in[0];
    const void*  edges   = d_in[1];
    const void*  mask    = d_in[2];
    const float* logp    = (const float*)d_in[3];
    const float* means   = (const float*)d_in[4];
    const float* logvars = (const float*)d_in[5];
    const float* W       = (const float*)d_in[6];
    const float* bias    = (const float*)d_in[7];
    float* out = (float*)d_out;

    int E = in_sizes[1] / 2;

    cudaFuncSetAttribute(gemm_mma_kernel, cudaFuncAttributeMaxDynamicSharedMemorySize, SM_TOTAL);

    detect_kernel<<<1, 256>>>(mask, edges);
    zero_kernel<<<(NNODES + 255) / 256, 256>>>();
    prep_kernel<<<NNODES, 256>>>(x, mask, logp, means, logvars);

    int eb = (E + 255) / 256;
    count_kernel<<<eb, 256>>>(edges, E);
    scan_kernel<<<1, 1024>>>();
    scatter_kernel<<<eb, 256>>>(edges, E);
    aggregate_kernel<<<NNODES, 256>>>(x);

    bprep_kernel<<<8 * 352, 256>>>(W, means, logvars);

    dim3 ggrid(8, (NNODES + 63) / 64);
    gemm_mma_kernel<<<ggrid, 256, SM_TOTAL>>>(bias, out);
}